// round 16
// baseline (speedup 1.0000x reference)
#include <cuda_runtime.h>
#include <cstdint>

#define Bz  8
#define Sz  256
#define Hz  128
#define HDz 32
#define BSz 2048
#define SCALE 0.17677669529663687f   // 1/sqrt(32)
#define TST 136                       // 64-row rel tile stride: conflict-free both phases
#define XPAD 129                      // proj input row stride

// __device__ scratch (allocation-free rule)
__device__ float g_Q[BSz * Hz];
__device__ float g_Keff[BSz * Hz];
__device__ float g_Veff[BSz * Hz];
__device__ float g_u[Bz * 2 * Sz * Hz];        // u[b,i,q][128]
__device__ float g_sbase[Bz * 4 * Sz * Sz];    // rel heads only
__device__ float g_probs[Bz * 4 * Sz * Sz];    // abs heads only (normalized)
__device__ float g_mred[Bz * 2 * Sz * 4 * 2];  // (m,l) per (b,i,q,quarter)
__device__ float g_wpart[Bz * 2 * Sz * 4 * Hz];// wacc per (b,i,q,quarter)[128]
__device__ float g_vpart[Bz * 2 * Sz * 4 * HDz];// vctx per (b,i,q,quarter)[32]
__device__ float g_ctx[BSz * Hz];

#define CP_ASYNC16(dst, src) \
    asm volatile("cp.async.cg.shared.global [%0], [%1], 16;\n" :: "r"(dst), "l"(src))
#define CP_COMMIT() asm volatile("cp.async.commit_group;\n" ::: "memory")
#define CP_WAIT0()  asm volatile("cp.async.wait_group 0;\n" ::: "memory")

// ---------------------------------------------------------------------------
// K0: projections, register-tiled. 16 rows/CTA (128 CTAs), 256 threads.
// ---------------------------------------------------------------------------
__global__ void __launch_bounds__(256, 2) proj_kernel(
        const float* __restrict__ X,
        const float* __restrict__ abs0,
        const float* __restrict__ abs1,
        const float* __restrict__ Wq, const float* __restrict__ bq,
        const float* __restrict__ Wk, const float* __restrict__ bk,
        const float* __restrict__ Wv, const float* __restrict__ bv) {
    int r0 = blockIdx.x * 16;
    int t = threadIdx.x;
    extern __shared__ float smp[];
    float* xs  = smp;                    // 16 * XPAD
    float* a0s = xs  + 16 * XPAD;
    float* a1s = a0s + 16 * XPAD;
    float* wts = a1s + 16 * XPAD;        // 3 * 32 * 128

    #pragma unroll
    for (int jj = 0; jj < 8; jj++) {
        int idx = jj * 256 + t;
        int row = idx >> 7, col = idx & 127;
        xs [row * XPAD + col] = X   [(r0 + row) * Hz + col];
        a0s[row * XPAD + col] = abs0[(r0 + row) * Hz + col];
        a1s[row * XPAD + col] = abs1[(r0 + row) * Hz + col];
    }

    int r = t & 15, jg = t >> 4;
    int j0 = jg * 8;
    bool fold = (jg < 8);
    const float* as = (jg < 4) ? a0s : a1s;

    float qa[8], ka[8], va[8];
    #pragma unroll
    for (int jj = 0; jj < 8; jj++) {
        qa[jj] = bq[j0 + jj];
        float bkv = bk[j0 + jj], bvv = bv[j0 + jj];
        ka[jj] = fold ? 2.f * bkv : bkv;
        va[jj] = fold ? 2.f * bvv : bvv;
    }

    for (int i0 = 0; i0 < Hz; i0 += 32) {
        __syncthreads();
        #pragma unroll
        for (int jj = 0; jj < 4; jj++) {
            int idx = jj * 256 + t;
            ((float4*)wts)[idx]               = ((const float4*)(Wq + i0 * Hz))[idx];
            ((float4*)(wts + 32 * Hz))[idx]   = ((const float4*)(Wk + i0 * Hz))[idx];
            ((float4*)(wts + 64 * Hz))[idx]   = ((const float4*)(Wv + i0 * Hz))[idx];
        }
        __syncthreads();
        #pragma unroll 8
        for (int ii = 0; ii < 32; ii++) {
            int i = i0 + ii;
            float x = xs[r * XPAD + i];
            float wq[8], wk8[8], wv8[8];
            *(float4*)&wq [0] = *(const float4*)&wts[ii * Hz + j0];
            *(float4*)&wq [4] = *(const float4*)&wts[ii * Hz + j0 + 4];
            *(float4*)&wk8[0] = *(const float4*)&wts[32 * Hz + ii * Hz + j0];
            *(float4*)&wk8[4] = *(const float4*)&wts[32 * Hz + ii * Hz + j0 + 4];
            *(float4*)&wv8[0] = *(const float4*)&wts[64 * Hz + ii * Hz + j0];
            *(float4*)&wv8[4] = *(const float4*)&wts[64 * Hz + ii * Hz + j0 + 4];
            #pragma unroll
            for (int jj = 0; jj < 8; jj++) {
                qa[jj] += x * wq[jj];
                ka[jj] += x * wk8[jj];
                va[jj] += x * wv8[jj];
            }
            if (fold) {
                float a = as[r * XPAD + i];
                #pragma unroll
                for (int jj = 0; jj < 8; jj++) {
                    ka[jj] += a * wk8[jj];
                    va[jj] += a * wv8[jj];
                }
            }
        }
    }

    int ro = r0 + r;
    *(float4*)&g_Q[ro * Hz + j0]        = *(float4*)&qa[0];
    *(float4*)&g_Q[ro * Hz + j0 + 4]    = *(float4*)&qa[4];
    *(float4*)&g_Keff[ro * Hz + j0]     = *(float4*)&ka[0];
    *(float4*)&g_Keff[ro * Hz + j0 + 4] = *(float4*)&ka[4];
    *(float4*)&g_Veff[ro * Hz + j0]     = *(float4*)&va[0];
    *(float4*)&g_Veff[ro * Hz + j0 + 4] = *(float4*)&va[4];
}

// ---------------------------------------------------------------------------
// K1: scores. Rel heads: sbase + u. Abs heads: softmax -> normalized probs.
// ---------------------------------------------------------------------------
__global__ void __launch_bounds__(256) sbase_kernel(const float* __restrict__ mask,
                                                    const float* __restrict__ Wk) {
    int qt = blockIdx.x, b = blockIdx.y, h = blockIdx.z;
    int t = threadIdx.x;
    extern __shared__ float smb[];
    float* Qs = smb;                  // 32*32
    float* ks = Qs + 32 * 32;         // 256*33
    float* ss = ks + 256 * 33;        // 32*257 (abs only)

    #pragma unroll
    for (int r = 0; r < 4; r++) {
        int idx = r * 256 + t;
        int qq = idx >> 5, c = idx & 31;
        Qs[idx] = g_Q[(b * Sz + qt * 32 + qq) * Hz + h * HDz + c];
    }
    #pragma unroll
    for (int jj = 0; jj < 8; jj++) {
        int idx = jj * 256 + t;
        int row = idx >> 3, c4 = idx & 7;
        float4 v = *(const float4*)&g_Keff[(b * Sz + row) * Hz + h * HDz + c4 * 4];
        ks[row * 33 + c4 * 4 + 0] = v.x;
        ks[row * 33 + c4 * 4 + 1] = v.y;
        ks[row * 33 + c4 * 4 + 2] = v.z;
        ks[row * 33 + c4 * 4 + 3] = v.w;
    }
    __syncthreads();

    float kr[32];
    #pragma unroll
    for (int c = 0; c < 32; c++) kr[c] = ks[t * 33 + c];

    int qbase = qt * 32;
    if (h >= 2) {
        #pragma unroll 2
        for (int qq = 0; qq < 32; qq++) {
            float acc = 0.f;
            #pragma unroll
            for (int c = 0; c < 32; c++) acc += Qs[qq * 32 + c] * kr[c];
            int q = qbase + qq;
            g_sbase[((b * 4 + h) * Sz + q) * Sz + t] =
                acc * SCALE + mask[(b * Sz + q) * Sz + t];
        }
        int j = t & 127, g2 = t >> 7;
        int i = h - 2;
        float wr[32];
        #pragma unroll
        for (int c4 = 0; c4 < 8; c4++)
            *(float4*)&wr[c4 * 4] = *(const float4*)&Wk[j * Hz + h * HDz + c4 * 4];
        #pragma unroll 4
        for (int qq = g2 * 16; qq < g2 * 16 + 16; qq++) {
            float acc = 0.f;
            #pragma unroll
            for (int c = 0; c < 32; c++) acc += wr[c] * Qs[qq * 32 + c];
            g_u[((b * 2 + i) * Sz + qbase + qq) * Hz + j] = acc;
        }
    } else {
        #pragma unroll 2
        for (int qq = 0; qq < 32; qq++) {
            float acc = 0.f;
            #pragma unroll
            for (int c = 0; c < 32; c++) acc += Qs[qq * 32 + c] * kr[c];
            int q = qbase + qq;
            ss[qq * 257 + t] = acc * SCALE + mask[(b * Sz + q) * Sz + t];
        }
        __syncthreads();
        int w = t >> 5, lane = t & 31;
        #pragma unroll
        for (int r = 0; r < 4; r++) {
            int row = w * 4 + r;
            float v[8];
            #pragma unroll
            for (int j = 0; j < 8; j++) v[j] = ss[row * 257 + lane + j * 32];
            float m = v[0];
            #pragma unroll
            for (int j = 1; j < 8; j++) m = fmaxf(m, v[j]);
            #pragma unroll
            for (int o = 16; o; o >>= 1) m = fmaxf(m, __shfl_xor_sync(~0u, m, o));
            float p[8], l = 0.f;
            #pragma unroll
            for (int j = 0; j < 8; j++) { p[j] = __expf(v[j] - m); l += p[j]; }
            #pragma unroll
            for (int o = 16; o; o >>= 1) l += __shfl_xor_sync(~0u, l, o);
            float inv = 1.f / l;
            int q = qbase + row;
            #pragma unroll
            for (int j = 0; j < 8; j++)
                g_probs[((b * 4 + h) * Sz + q) * Sz + lane + j * 32] = p[j] * inv;
        }
    }
}

// ---------------------------------------------------------------------------
// K2: rel split-K (quarters, 64 keys/CTA). CTA per (q, b, i*4+quarter);
// 128 threads, 6 CTAs/SM. Also computes the quarter-partial P·V (vctx).
// ---------------------------------------------------------------------------
__global__ void __launch_bounds__(128, 6) rel_kernel(
        const float* __restrict__ rel0, const float* __restrict__ rel1) {
    int q = blockIdx.x, b = blockIdx.y;
    int i = blockIdx.z >> 2, quarter = blockIdx.z & 3;
    int hr = 2 + i;
    int kbase = quarter * 64;
    int t = threadIdx.x, lane = t & 31, w = t >> 5;

    extern __shared__ float sm[];
    float* tile = sm;                 // [64][TST]
    float* uvec = sm + 64 * TST;      // 128
    float* kb   = uvec + 128;         // 64
    float* pc   = kb + 64;            // 64
    float* wm   = pc + 64;            // 4
    float* wl   = wm + 4;             // 4
    float* vp   = wl + 4;             // 128 (4 warps x 32 ch)

    // 1) issue all loads: warp w rows 16w..16w+15, lane = float4 col
    const float4* rp4 = (const float4*)(((i == 0) ? rel0 : rel1)
                        + (size_t)(b * Sz + q) * Sz * Hz) + (size_t)kbase * 32;
    uint32_t tileu = (uint32_t)__cvta_generic_to_shared(tile);
    #pragma unroll
    for (int r = 0; r < 16; r++) {
        int row = w * 16 + r;
        uint32_t d = tileu + (uint32_t)(row * TST + lane * 4) * 4;
        CP_ASYNC16(d, rp4 + row * 32 + lane);
    }
    CP_COMMIT();

    // 2) prologue (overlaps DRAM)
    uvec[t] = g_u[((b * 2 + i) * Sz + q) * Hz + t];
    if (t < 64) kb[t] = g_sbase[((b * 4 + hr) * Sz + q) * Sz + kbase + t];
    __syncthreads();

    // 3) per-warp wait + score: key = t>>1, part = t&1
    CP_WAIT0();
    __syncwarp();
    int key = t >> 1, part = t & 1;
    float s;
    {
        const float4* row = (const float4*)&tile[key * TST + part * 4];
        const float4* up  = (const float4*)&uvec[part * 4];
        float acc = 0.f;
        #pragma unroll
        for (int j = 0; j < 16; j++) {
            float4 r = row[j * 2], u = up[j * 2];
            acc += r.x * u.x + r.y * u.y + r.z * u.z + r.w * u.w;
        }
        acc += __shfl_xor_sync(~0u, acc, 1);
        s = acc * SCALE + kb[key];
    }
    float mw = s;
    #pragma unroll
    for (int o = 16; o; o >>= 1) mw = fmaxf(mw, __shfl_xor_sync(~0u, mw, o));
    if (lane == 0) wm[w] = mw;
    __syncthreads();

    // 4) quarter-local max, p, quarter-local sum
    float M = fmaxf(fmaxf(wm[0], wm[1]), fmaxf(wm[2], wm[3]));
    float p = __expf(s - M);
    if (part == 0) pc[key] = p;
    float lw = (part == 0) ? p : 0.f;
    #pragma unroll
    for (int o = 16; o; o >>= 1) lw += __shfl_xor_sync(~0u, lw, o);
    if (lane == 0) wl[w] = lw;
    __syncthreads();
    float L = wl[0] + wl[1] + wl[2] + wl[3];

    if (t == 0) {
        int mi = ((b * 2 + i) * Sz + q) * 4 + quarter;
        g_mred[mi * 2 + 0] = M;
        g_mred[mi * 2 + 1] = L;
    }

    // 5a) vctx partial: warp w sums keys 16w..16w+15; lane = channel.
    {
        float va = 0.f;
        const float* vb = &g_Veff[(b * Sz + kbase + w * 16) * Hz + hr * HDz + lane];
        const float* pw = &pc[w * 16];
        #pragma unroll
        for (int k = 0; k < 16; k++)
            va += pw[k] * vb[k * Hz];
        vp[w * 32 + lane] = va;
    }

    // 5b) wacc[ch] = sum_k pc[k] * tile[k][ch]  (thread = channel)
    {
        float wacc = 0.f;
        #pragma unroll 8
        for (int k = 0; k < 64; k++)
            wacc += pc[k] * tile[k * TST + t];
        g_wpart[(((b * 2 + i) * Sz + q) * 4 + quarter) * Hz + t] = wacc;
    }
    __syncthreads();
    if (t < HDz)
        g_vpart[(((b * 2 + i) * Sz + q) * 4 + quarter) * HDz + t] =
            vp[t] + vp[32 + t] + vp[64 + t] + vp[96 + t];
}

// ---------------------------------------------------------------------------
// K2b: combine, batched (16 q/CTA). Merges 4 quarters of (m,l,wacc,vctx),
// projects w through Wv_hr, writes the rel ctx slice directly.
// ---------------------------------------------------------------------------
__global__ void __launch_bounds__(256) combine_kernel(
        const float* __restrict__ Wv, const float* __restrict__ bv) {
    int qt = blockIdx.x, b = blockIdx.y, i = blockIdx.z;
    int hr = 2 + i;
    int qbase = qt * 16;
    int t = threadIdx.x;

    extern __shared__ float smc[];
    float* wv   = smc;               // 128*33 = 4224
    float* wfin = wv + 128 * 33;     // 16*130 = 2080
    float* wout = wfin + 16 * 130;   // 16*33  = 528
    float* misc = wout + 16 * 33;    // 192: scales[64], mraw[128]

    if (t < 128) misc[64 + t] = g_mred[((b * 2 + i) * Sz + qbase) * 8 + t];
    #pragma unroll
    for (int jj = 0; jj < 4; jj++) {
        int idx = jj * 256 + t;      // 1024 float4
        int row = idx >> 3, c4 = idx & 7;
        float4 v = *(const float4*)&Wv[row * Hz + hr * HDz + c4 * 4];
        wv[row * 33 + c4 * 4 + 0] = v.x;
        wv[row * 33 + c4 * 4 + 1] = v.y;
        wv[row * 33 + c4 * 4 + 2] = v.z;
        wv[row * 33 + c4 * 4 + 3] = v.w;
    }
    __syncthreads();

    if (t < 16) {
        const float* mr = &misc[64 + t * 8];
        float m0 = mr[0], l0 = mr[1], m1 = mr[2], l1 = mr[3];
        float m2 = mr[4], l2 = mr[5], m3 = mr[6], l3 = mr[7];
        float M = fmaxf(fmaxf(m0, m1), fmaxf(m2, m3));
        float c0 = __expf(m0 - M), c1 = __expf(m1 - M);
        float c2 = __expf(m2 - M), c3 = __expf(m3 - M);
        float invL = 1.f / (l0 * c0 + l1 * c1 + l2 * c2 + l3 * c3);
        misc[t * 4 + 0] = c0 * invL;
        misc[t * 4 + 1] = c1 * invL;
        misc[t * 4 + 2] = c2 * invL;
        misc[t * 4 + 3] = c3 * invL;
    }
    __syncthreads();

    // merge wacc quarters (normalized)
    #pragma unroll
    for (int jj = 0; jj < 8; jj++) {
        int idx = jj * 256 + t;      // 2048
        int q = idx >> 7, ch = idx & 127;
        int base = (((b * 2 + i) * Sz + qbase + q) * 4) * Hz;
        wfin[q * 130 + ch] = g_wpart[base + ch]          * misc[q * 4 + 0]
                           + g_wpart[base + Hz + ch]     * misc[q * 4 + 1]
                           + g_wpart[base + 2 * Hz + ch] * misc[q * 4 + 2]
                           + g_wpart[base + 3 * Hz + ch] * misc[q * 4 + 3];
    }
    __syncthreads();

    // projection into wout: thread q = t>>4, 2 channels cc=(t&15)*2
    {
        int q = t >> 4, cc = (t & 15) * 2;
        float a0 = bv[hr * HDz + cc], a1 = bv[hr * HDz + cc + 1];
        #pragma unroll 8
        for (int ch = 0; ch < 128; ch++) {
            float wf = wfin[q * 130 + ch];
            a0 += wf * wv[ch * 33 + cc];
            a1 += wf * wv[ch * 33 + cc + 1];
        }
        wout[q * 33 + cc]     = a0;
        wout[q * 33 + cc + 1] = a1;
    }
    __syncthreads();

    // final: ctx_rel = wout + merged vctx
    #pragma unroll
    for (int jj = 0; jj < 2; jj++) {
        int idx = jj * 256 + t;      // 512
        int q = idx >> 5, c = idx & 31;
        int base = (((b * 2 + i) * Sz + qbase + q) * 4) * HDz;
        float v = g_vpart[base + c]           * misc[q * 4 + 0]
                + g_vpart[base + HDz + c]     * misc[q * 4 + 1]
                + g_vpart[base + 2 * HDz + c] * misc[q * 4 + 2]
                + g_vpart[base + 3 * HDz + c] * misc[q * 4 + 3];
        g_ctx[(b * Sz + qbase + q) * Hz + hr * HDz + c] = wout[q * 33 + c] + v;
    }
}

// ---------------------------------------------------------------------------
// K3: ctx = probs @ Veff, ABS HEADS ONLY. grid (16,8,2), 256 thr, 16 q/CTA.
// ---------------------------------------------------------------------------
__global__ void __launch_bounds__(256) ctxv_kernel() {
    int qt = blockIdx.x, b = blockIdx.y, h = blockIdx.z;   // h in {0,1}
    int qbase = qt * 16;
    int t = threadIdx.x;
    extern __shared__ float sm3[];
    float* Vs = sm3;                        // 256*33
    float* Ps = sm3 + 256 * 33;             // 16*256

    #pragma unroll
    for (int jj = 0; jj < 8; jj++) {
        int idx = jj * 256 + t;
        int row = idx >> 3, c4 = idx & 7;
        float4 v = *(const float4*)&g_Veff[(b * Sz + row) * Hz + h * HDz + c4 * 4];
        Vs[row * 33 + c4 * 4 + 0] = v.x;
        Vs[row * 33 + c4 * 4 + 1] = v.y;
        Vs[row * 33 + c4 * 4 + 2] = v.z;
        Vs[row * 33 + c4 * 4 + 3] = v.w;
    }
    #pragma unroll
    for (int jj = 0; jj < 4; jj++) {
        int idx = jj * 256 + t;                  // 1024 float4
        int qq = idx >> 6, k4 = idx & 63;
        float4 v = *(const float4*)&g_probs[((b * 4 + h) * Sz + qbase + qq) * Sz + k4 * 4];
        *(float4*)&Ps[qq * 256 + k4 * 4] = v;
    }
    __syncthreads();

    int c = t & 31, g = t >> 5;                  // 8 groups x 2 q each
    const float4* Ps4 = (const float4*)Ps;
    float acc0 = 0.f, acc1 = 0.f;
    #pragma unroll 4
    for (int k4 = 0; k4 < 64; k4++) {
        float v0 = Vs[(k4 * 4 + 0) * 33 + c];
        float v1 = Vs[(k4 * 4 + 1) * 33 + c];
        float v2 = Vs[(k4 * 4 + 2) * 33 + c];
        float v3 = Vs[(k4 * 4 + 3) * 33 + c];
        float4 P0 = Ps4[(g * 2 + 0) * 64 + k4];
        float4 P1 = Ps4[(g * 2 + 1) * 64 + k4];
        acc0 += P0.x * v0 + P0.y * v1 + P0.z * v2 + P0.w * v3;
        acc1 += P1.x * v0 + P1.y * v1 + P1.z * v2 + P1.w * v3;
    }
    #pragma unroll
    for (int r = 0; r < 2; r++) {
        int q = qbase + g * 2 + r;
        g_ctx[(b * Sz + q) * Hz + h * HDz + c] = (r == 0) ? acc0 : acc1;
    }
}

// ---------------------------------------------------------------------------
// K4: out = ctx @ Wo + bo. Wo staged in smem; 16 rows/CTA, 256 threads.
// ---------------------------------------------------------------------------
__global__ void __launch_bounds__(256) out_kernel(const float* __restrict__ Wo,
                                                  const float* __restrict__ bo,
                                                  float* __restrict__ out) {
    int r0 = blockIdx.x * 16;
    int t = threadIdx.x;
    extern __shared__ float sm4[];
    float* ws = sm4;                 // 128*128
    float* xs = sm4 + Hz * Hz;       // 16*128

    #pragma unroll
    for (int jj = 0; jj < 16; jj++) {
        int idx = jj * 256 + t;
        *(float4*)&ws[idx * 4] = *(const float4*)&Wo[idx * 4];
    }
    #pragma unroll
    for (int jj = 0; jj < 2; jj++) {
        int idx = jj * 256 + t;
        *(float4*)&xs[idx * 4] = *(const float4*)&g_ctx[r0 * Hz + idx * 4];
    }
    __syncthreads();

    int j = t & 127, rbase = (t >> 7) * 8;
    float a[8];
    float bj = bo[j];
    #pragma unroll
    for (int r = 0; r < 8; r++) a[r] = bj;
    #pragma unroll 4
    for (int i = 0; i < Hz; i++) {
        float w = ws[i * Hz + j];
        #pragma unroll
        for (int r = 0; r < 8; r++)
            a[r] += xs[(rbase + r) * Hz + i] * w;
    }
    #pragma unroll
    for (int r = 0; r < 8; r++)
        out[(r0 + rbase + r) * Hz + j] = a[r];
}

// ---------------------------------------------------------------------------
extern "C" void kernel_launch(void* const* d_in, const int* in_sizes, int n_in,
                              void* d_out, int out_size) {
    const float* X    = (const float*)d_in[0];
    const float* mask = (const float*)d_in[1];
    const float* abs0 = (const float*)d_in[2];
    const float* abs1 = (const float*)d_in[3];
    const float* rel0 = (const float*)d_in[4];
    const float* rel1 = (const float*)d_in[5];
    const float* Wq   = (const float*)d_in[6];
    const float* bq   = (const float*)d_in[7];
    const float* Wk   = (const float*)d_in[8];
    const float* bk   = (const float*)d_in[9];
    const float* Wv   = (const float*)d_in[10];
    const float* bv   = (const float*)d_in[11];
    const float* Wo   = (const float*)d_in[12];
    const float* bo   = (const float*)d_in[13];
    float* out = (float*)d_out;

    size_t prsm  = (size_t)(3 * 16 * XPAD + 3 * 32 * Hz) * sizeof(float);
    size_t sbsm  = (size_t)(32 * 32 + 256 * 33 + 32 * 257) * sizeof(float);
    size_t relsm = (size_t)(64 * TST + 128 + 64 + 64 + 4 + 4 + 128) * sizeof(float);
    size_t cbsm  = (size_t)(128 * 33 + 16 * 130 + 16 * 33 + 192) * sizeof(float);
    size_t ctxsm = (size_t)(256 * 33 + 16 * 256) * sizeof(float);
    size_t outsm = (size_t)(Hz * Hz + 16 * Hz) * sizeof(float);
    cudaFuncSetAttribute(proj_kernel,    cudaFuncAttributeMaxDynamicSharedMemorySize, (int)prsm);
    cudaFuncSetAttribute(sbase_kernel,   cudaFuncAttributeMaxDynamicSharedMemorySize, (int)sbsm);
    cudaFuncSetAttribute(rel_kernel,     cudaFuncAttributeMaxDynamicSharedMemorySize, (int)relsm);
    cudaFuncSetAttribute(combine_kernel, cudaFuncAttributeMaxDynamicSharedMemorySize, (int)cbsm);
    cudaFuncSetAttribute(ctxv_kernel,    cudaFuncAttributeMaxDynamicSharedMemorySize, (int)ctxsm);
    cudaFuncSetAttribute(out_kernel,     cudaFuncAttributeMaxDynamicSharedMemorySize, (int)outsm);

    proj_kernel<<<BSz / 16, 256, prsm>>>(X, abs0, abs1, Wq, bq, Wk, bk, Wv, bv);
    dim3 gs(8, Bz, 4);
    sbase_kernel<<<gs, 256, sbsm>>>(mask, Wk);
    dim3 gr(Sz, Bz, 8);                        // z = i*4 + quarter
    rel_kernel<<<gr, 128, relsm>>>(rel0, rel1);
    dim3 gc(16, Bz, 2);
    combine_kernel<<<gc, 256, cbsm>>>(Wv, bv);
    dim3 gv(16, Bz, 2);                        // abs heads only
    ctxv_kernel<<<gv, 256, ctxsm>>>();
    out_kernel<<<BSz / 16, 256, outsm>>>(Wo, bo, out);
}

// round 17
// speedup vs baseline: 1.0569x; 1.0569x over previous
#include <cuda_runtime.h>
#include <cstdint>

#define Bz  8
#define Sz  256
#define Hz  128
#define HDz 32
#define BSz 2048
#define SCALE 0.17677669529663687f   // 1/sqrt(32)
#define TST 136                       // 64-row rel tile stride: conflict-free both phases
#define XPAD 129                      // proj input row stride
#define SST 260                       // abs score/prob row stride (16B-aligned, conflict-free)

// __device__ scratch (allocation-free rule)
__device__ float g_Q[BSz * Hz];
__device__ float g_Keff[BSz * Hz];
__device__ float g_Veff[BSz * Hz];
__device__ float g_u[Bz * 2 * Sz * Hz];         // u[b,i,q][128]
__device__ float g_sbase[Bz * 4 * Sz * Sz];     // rel heads only
__device__ float g_mred[Bz * 2 * Sz * 4 * 2];   // (m,l) per (b,i,q,quarter)
__device__ float g_wpart[Bz * 2 * Sz * 4 * Hz]; // wacc per (b,i,q,quarter)[128]
__device__ float g_vpart[Bz * 2 * Sz * 4 * HDz];// vctx per (b,i,q,quarter)[32]
__device__ float g_ctx[BSz * Hz];

#define CP_ASYNC16(dst, src) \
    asm volatile("cp.async.cg.shared.global [%0], [%1], 16;\n" :: "r"(dst), "l"(src))
#define CP_COMMIT() asm volatile("cp.async.commit_group;\n" ::: "memory")
#define CP_WAIT0()  asm volatile("cp.async.wait_group 0;\n" ::: "memory")

// ---------------------------------------------------------------------------
// K0: projections, register-tiled. 16 rows/CTA (128 CTAs), 256 threads.
// ---------------------------------------------------------------------------
__global__ void __launch_bounds__(256, 2) proj_kernel(
        const float* __restrict__ X,
        const float* __restrict__ abs0,
        const float* __restrict__ abs1,
        const float* __restrict__ Wq, const float* __restrict__ bq,
        const float* __restrict__ Wk, const float* __restrict__ bk,
        const float* __restrict__ Wv, const float* __restrict__ bv) {
    int r0 = blockIdx.x * 16;
    int t = threadIdx.x;
    extern __shared__ float smp[];
    float* xs  = smp;                    // 16 * XPAD
    float* a0s = xs  + 16 * XPAD;
    float* a1s = a0s + 16 * XPAD;
    float* wts = a1s + 16 * XPAD;        // 3 * 32 * 128

    #pragma unroll
    for (int jj = 0; jj < 8; jj++) {
        int idx = jj * 256 + t;
        int row = idx >> 7, col = idx & 127;
        xs [row * XPAD + col] = X   [(r0 + row) * Hz + col];
        a0s[row * XPAD + col] = abs0[(r0 + row) * Hz + col];
        a1s[row * XPAD + col] = abs1[(r0 + row) * Hz + col];
    }

    int r = t & 15, jg = t >> 4;
    int j0 = jg * 8;
    bool fold = (jg < 8);
    const float* as = (jg < 4) ? a0s : a1s;

    float qa[8], ka[8], va[8];
    #pragma unroll
    for (int jj = 0; jj < 8; jj++) {
        qa[jj] = bq[j0 + jj];
        float bkv = bk[j0 + jj], bvv = bv[j0 + jj];
        ka[jj] = fold ? 2.f * bkv : bkv;
        va[jj] = fold ? 2.f * bvv : bvv;
    }

    for (int i0 = 0; i0 < Hz; i0 += 32) {
        __syncthreads();
        #pragma unroll
        for (int jj = 0; jj < 4; jj++) {
            int idx = jj * 256 + t;
            ((float4*)wts)[idx]               = ((const float4*)(Wq + i0 * Hz))[idx];
            ((float4*)(wts + 32 * Hz))[idx]   = ((const float4*)(Wk + i0 * Hz))[idx];
            ((float4*)(wts + 64 * Hz))[idx]   = ((const float4*)(Wv + i0 * Hz))[idx];
        }
        __syncthreads();
        #pragma unroll 8
        for (int ii = 0; ii < 32; ii++) {
            int i = i0 + ii;
            float x = xs[r * XPAD + i];
            float wq[8], wk8[8], wv8[8];
            *(float4*)&wq [0] = *(const float4*)&wts[ii * Hz + j0];
            *(float4*)&wq [4] = *(const float4*)&wts[ii * Hz + j0 + 4];
            *(float4*)&wk8[0] = *(const float4*)&wts[32 * Hz + ii * Hz + j0];
            *(float4*)&wk8[4] = *(const float4*)&wts[32 * Hz + ii * Hz + j0 + 4];
            *(float4*)&wv8[0] = *(const float4*)&wts[64 * Hz + ii * Hz + j0];
            *(float4*)&wv8[4] = *(const float4*)&wts[64 * Hz + ii * Hz + j0 + 4];
            #pragma unroll
            for (int jj = 0; jj < 8; jj++) {
                qa[jj] += x * wq[jj];
                ka[jj] += x * wk8[jj];
                va[jj] += x * wv8[jj];
            }
            if (fold) {
                float a = as[r * XPAD + i];
                #pragma unroll
                for (int jj = 0; jj < 8; jj++) {
                    ka[jj] += a * wk8[jj];
                    va[jj] += a * wv8[jj];
                }
            }
        }
    }

    int ro = r0 + r;
    *(float4*)&g_Q[ro * Hz + j0]        = *(float4*)&qa[0];
    *(float4*)&g_Q[ro * Hz + j0 + 4]    = *(float4*)&qa[4];
    *(float4*)&g_Keff[ro * Hz + j0]     = *(float4*)&ka[0];
    *(float4*)&g_Keff[ro * Hz + j0 + 4] = *(float4*)&ka[4];
    *(float4*)&g_Veff[ro * Hz + j0]     = *(float4*)&va[0];
    *(float4*)&g_Veff[ro * Hz + j0 + 4] = *(float4*)&va[4];
}

// ---------------------------------------------------------------------------
// K1: scores. Rel heads (h>=2): sbase + u. Abs heads (h<2): softmax AND the
// full P·V context, written straight to g_ctx (ks reused for Veff slice).
// grid (8,8,4), 256 threads.
// ---------------------------------------------------------------------------
__global__ void __launch_bounds__(256) sbase_kernel(const float* __restrict__ mask,
                                                    const float* __restrict__ Wk) {
    int qt = blockIdx.x, b = blockIdx.y, h = blockIdx.z;
    int t = threadIdx.x;
    extern __shared__ float smb[];
    float* Qs = smb;                  // 32*32   = 1024
    float* ks = Qs + 32 * 32;         // 256*33  = 8448 (Keff, then Veff for abs)
    float* ss = ks + 256 * 33;        // 32*SST  = 8320 (abs only: scores -> probs)

    #pragma unroll
    for (int r = 0; r < 4; r++) {
        int idx = r * 256 + t;
        int qq = idx >> 5, c = idx & 31;
        Qs[idx] = g_Q[(b * Sz + qt * 32 + qq) * Hz + h * HDz + c];
    }
    #pragma unroll
    for (int jj = 0; jj < 8; jj++) {
        int idx = jj * 256 + t;
        int row = idx >> 3, c4 = idx & 7;
        float4 v = *(const float4*)&g_Keff[(b * Sz + row) * Hz + h * HDz + c4 * 4];
        ks[row * 33 + c4 * 4 + 0] = v.x;
        ks[row * 33 + c4 * 4 + 1] = v.y;
        ks[row * 33 + c4 * 4 + 2] = v.z;
        ks[row * 33 + c4 * 4 + 3] = v.w;
    }
    __syncthreads();

    float kr[32];
    #pragma unroll
    for (int c = 0; c < 32; c++) kr[c] = ks[t * 33 + c];

    int qbase = qt * 32;
    if (h >= 2) {
        #pragma unroll 2
        for (int qq = 0; qq < 32; qq++) {
            float acc = 0.f;
            #pragma unroll
            for (int c = 0; c < 32; c++) acc += Qs[qq * 32 + c] * kr[c];
            int q = qbase + qq;
            g_sbase[((b * 4 + h) * Sz + q) * Sz + t] =
                acc * SCALE + mask[(b * Sz + q) * Sz + t];
        }
        int j = t & 127, g2 = t >> 7;
        int i = h - 2;
        float wr[32];
        #pragma unroll
        for (int c4 = 0; c4 < 8; c4++)
            *(float4*)&wr[c4 * 4] = *(const float4*)&Wk[j * Hz + h * HDz + c4 * 4];
        #pragma unroll 4
        for (int qq = g2 * 16; qq < g2 * 16 + 16; qq++) {
            float acc = 0.f;
            #pragma unroll
            for (int c = 0; c < 32; c++) acc += wr[c] * Qs[qq * 32 + c];
            g_u[((b * 2 + i) * Sz + qbase + qq) * Hz + j] = acc;
        }
    } else {
        #pragma unroll 2
        for (int qq = 0; qq < 32; qq++) {
            float acc = 0.f;
            #pragma unroll
            for (int c = 0; c < 32; c++) acc += Qs[qq * 32 + c] * kr[c];
            int q = qbase + qq;
            ss[qq * SST + t] = acc * SCALE + mask[(b * Sz + q) * Sz + t];
        }
        __syncthreads();
        // softmax: 8 warps x 4 q-rows; normalized probs written back in-place
        int w = t >> 5, lane = t & 31;
        #pragma unroll
        for (int r = 0; r < 4; r++) {
            int row = w * 4 + r;
            float v[8];
            #pragma unroll
            for (int j = 0; j < 8; j++) v[j] = ss[row * SST + lane + j * 32];
            float m = v[0];
            #pragma unroll
            for (int j = 1; j < 8; j++) m = fmaxf(m, v[j]);
            #pragma unroll
            for (int o = 16; o; o >>= 1) m = fmaxf(m, __shfl_xor_sync(~0u, m, o));
            float p[8], l = 0.f;
            #pragma unroll
            for (int j = 0; j < 8; j++) { p[j] = __expf(v[j] - m); l += p[j]; }
            #pragma unroll
            for (int o = 16; o; o >>= 1) l += __shfl_xor_sync(~0u, l, o);
            float inv = 1.f / l;
            #pragma unroll
            for (int j = 0; j < 8; j++)
                ss[row * SST + lane + j * 32] = p[j] * inv;
        }
        __syncthreads();
        // re-stage ks with the Veff head-slice (Keff fully consumed)
        #pragma unroll
        for (int jj = 0; jj < 8; jj++) {
            int idx = jj * 256 + t;
            int row = idx >> 3, c4 = idx & 7;
            float4 v = *(const float4*)&g_Veff[(b * Sz + row) * Hz + h * HDz + c4 * 4];
            ks[row * 33 + c4 * 4 + 0] = v.x;
            ks[row * 33 + c4 * 4 + 1] = v.y;
            ks[row * 33 + c4 * 4 + 2] = v.z;
            ks[row * 33 + c4 * 4 + 3] = v.w;
        }
        __syncthreads();
        // ctx_abs = P @ Veff : warp g handles 4 q, lane = channel
        int c = t & 31, g = t >> 5;
        float a0 = 0.f, a1 = 0.f, a2 = 0.f, a3 = 0.f;
        #pragma unroll 4
        for (int k4 = 0; k4 < 64; k4++) {
            float v0 = ks[(k4 * 4 + 0) * 33 + c];
            float v1 = ks[(k4 * 4 + 1) * 33 + c];
            float v2 = ks[(k4 * 4 + 2) * 33 + c];
            float v3 = ks[(k4 * 4 + 3) * 33 + c];
            float4 P0 = *(const float4*)&ss[(g * 4 + 0) * SST + k4 * 4];
            float4 P1 = *(const float4*)&ss[(g * 4 + 1) * SST + k4 * 4];
            float4 P2 = *(const float4*)&ss[(g * 4 + 2) * SST + k4 * 4];
            float4 P3 = *(const float4*)&ss[(g * 4 + 3) * SST + k4 * 4];
            a0 += P0.x * v0 + P0.y * v1 + P0.z * v2 + P0.w * v3;
            a1 += P1.x * v0 + P1.y * v1 + P1.z * v2 + P1.w * v3;
            a2 += P2.x * v0 + P2.y * v1 + P2.z * v2 + P2.w * v3;
            a3 += P3.x * v0 + P3.y * v1 + P3.z * v2 + P3.w * v3;
        }
        #pragma unroll
        for (int r = 0; r < 4; r++) {
            int q = qbase + g * 4 + r;
            float a = (r == 0) ? a0 : (r == 1) ? a1 : (r == 2) ? a2 : a3;
            g_ctx[(b * Sz + q) * Hz + h * HDz + c] = a;
        }
    }
}

// ---------------------------------------------------------------------------
// K2: rel split-K (quarters, 64 keys/CTA). CTA per (q, b, i*4+quarter);
// 128 threads, 6 CTAs/SM. Also computes the quarter-partial P·V (vctx).
// ---------------------------------------------------------------------------
__global__ void __launch_bounds__(128, 6) rel_kernel(
        const float* __restrict__ rel0, const float* __restrict__ rel1) {
    int q = blockIdx.x, b = blockIdx.y;
    int i = blockIdx.z >> 2, quarter = blockIdx.z & 3;
    int hr = 2 + i;
    int kbase = quarter * 64;
    int t = threadIdx.x, lane = t & 31, w = t >> 5;

    extern __shared__ float sm[];
    float* tile = sm;                 // [64][TST]
    float* uvec = sm + 64 * TST;      // 128
    float* kb   = uvec + 128;         // 64
    float* pc   = kb + 64;            // 64
    float* wm   = pc + 64;            // 4
    float* wl   = wm + 4;             // 4
    float* vp   = wl + 4;             // 128 (4 warps x 32 ch)

    const float4* rp4 = (const float4*)(((i == 0) ? rel0 : rel1)
                        + (size_t)(b * Sz + q) * Sz * Hz) + (size_t)kbase * 32;
    uint32_t tileu = (uint32_t)__cvta_generic_to_shared(tile);
    #pragma unroll
    for (int r = 0; r < 16; r++) {
        int row = w * 16 + r;
        uint32_t d = tileu + (uint32_t)(row * TST + lane * 4) * 4;
        CP_ASYNC16(d, rp4 + row * 32 + lane);
    }
    CP_COMMIT();

    uvec[t] = g_u[((b * 2 + i) * Sz + q) * Hz + t];
    if (t < 64) kb[t] = g_sbase[((b * 4 + hr) * Sz + q) * Sz + kbase + t];
    __syncthreads();

    CP_WAIT0();
    __syncwarp();
    int key = t >> 1, part = t & 1;
    float s;
    {
        const float4* row = (const float4*)&tile[key * TST + part * 4];
        const float4* up  = (const float4*)&uvec[part * 4];
        float acc = 0.f;
        #pragma unroll
        for (int j = 0; j < 16; j++) {
            float4 r = row[j * 2], u = up[j * 2];
            acc += r.x * u.x + r.y * u.y + r.z * u.z + r.w * u.w;
        }
        acc += __shfl_xor_sync(~0u, acc, 1);
        s = acc * SCALE + kb[key];
    }
    float mw = s;
    #pragma unroll
    for (int o = 16; o; o >>= 1) mw = fmaxf(mw, __shfl_xor_sync(~0u, mw, o));
    if (lane == 0) wm[w] = mw;
    __syncthreads();

    float M = fmaxf(fmaxf(wm[0], wm[1]), fmaxf(wm[2], wm[3]));
    float p = __expf(s - M);
    if (part == 0) pc[key] = p;
    float lw = (part == 0) ? p : 0.f;
    #pragma unroll
    for (int o = 16; o; o >>= 1) lw += __shfl_xor_sync(~0u, lw, o);
    if (lane == 0) wl[w] = lw;
    __syncthreads();
    float L = wl[0] + wl[1] + wl[2] + wl[3];

    if (t == 0) {
        int mi = ((b * 2 + i) * Sz + q) * 4 + quarter;
        g_mred[mi * 2 + 0] = M;
        g_mred[mi * 2 + 1] = L;
    }

    // vctx partial: warp w sums keys 16w..16w+15; lane = channel
    {
        float va = 0.f;
        const float* vb = &g_Veff[(b * Sz + kbase + w * 16) * Hz + hr * HDz + lane];
        const float* pw = &pc[w * 16];
        #pragma unroll
        for (int k = 0; k < 16; k++)
            va += pw[k] * vb[k * Hz];
        vp[w * 32 + lane] = va;
    }

    // wacc[ch] = sum_k pc[k] * tile[k][ch]
    {
        float wacc = 0.f;
        #pragma unroll 8
        for (int k = 0; k < 64; k++)
            wacc += pc[k] * tile[k * TST + t];
        g_wpart[(((b * 2 + i) * Sz + q) * 4 + quarter) * Hz + t] = wacc;
    }
    __syncthreads();
    if (t < HDz)
        g_vpart[(((b * 2 + i) * Sz + q) * 4 + quarter) * HDz + t] =
            vp[t] + vp[32 + t] + vp[64 + t] + vp[96 + t];
}

// ---------------------------------------------------------------------------
// K2b: combine, batched 8 q/CTA (512 CTAs). Merges quarters of
// (m,l,wacc,vctx), projects w through Wv_hr, writes rel ctx slice.
// ---------------------------------------------------------------------------
__global__ void __launch_bounds__(256) combine_kernel(
        const float* __restrict__ Wv, const float* __restrict__ bv) {
    int qt = blockIdx.x, b = blockIdx.y, i = blockIdx.z;
    int hr = 2 + i;
    int qbase = qt * 8;
    int t = threadIdx.x;

    extern __shared__ float smc[];
    float* wv   = smc;               // 128*33 = 4224
    float* wfin = wv + 128 * 33;     // 8*130  = 1040
    float* misc = wfin + 8 * 130;    // 96: scales[32], mraw[64]

    if (t < 64) misc[32 + t] = g_mred[((b * 2 + i) * Sz + qbase) * 8 + t];
    #pragma unroll
    for (int jj = 0; jj < 4; jj++) {
        int idx = jj * 256 + t;      // 1024 float4
        int row = idx >> 3, c4 = idx & 7;
        float4 v = *(const float4*)&Wv[row * Hz + hr * HDz + c4 * 4];
        wv[row * 33 + c4 * 4 + 0] = v.x;
        wv[row * 33 + c4 * 4 + 1] = v.y;
        wv[row * 33 + c4 * 4 + 2] = v.z;
        wv[row * 33 + c4 * 4 + 3] = v.w;
    }
    __syncthreads();

    if (t < 8) {
        const float* mr = &misc[32 + t * 8];
        float m0 = mr[0], l0 = mr[1], m1 = mr[2], l1 = mr[3];
        float m2 = mr[4], l2 = mr[5], m3 = mr[6], l3 = mr[7];
        float M = fmaxf(fmaxf(m0, m1), fmaxf(m2, m3));
        float c0 = __expf(m0 - M), c1 = __expf(m1 - M);
        float c2 = __expf(m2 - M), c3 = __expf(m3 - M);
        float invL = 1.f / (l0 * c0 + l1 * c1 + l2 * c2 + l3 * c3);
        misc[t * 4 + 0] = c0 * invL;
        misc[t * 4 + 1] = c1 * invL;
        misc[t * 4 + 2] = c2 * invL;
        misc[t * 4 + 3] = c3 * invL;
    }
    __syncthreads();

    // merge wacc quarters (normalized): 8 q x 128 ch = 1024
    #pragma unroll
    for (int jj = 0; jj < 4; jj++) {
        int idx = jj * 256 + t;
        int q = idx >> 7, ch = idx & 127;
        int base = (((b * 2 + i) * Sz + qbase + q) * 4) * Hz;
        wfin[q * 130 + ch] = g_wpart[base + ch]          * misc[q * 4 + 0]
                           + g_wpart[base + Hz + ch]     * misc[q * 4 + 1]
                           + g_wpart[base + 2 * Hz + ch] * misc[q * 4 + 2]
                           + g_wpart[base + 3 * Hz + ch] * misc[q * 4 + 3];
    }
    __syncthreads();

    // projection + vctx merge + final write: thread = (q = t>>5, c = t&31)
    {
        int q = t >> 5, c = t & 31;
        float a = bv[hr * HDz + c];
        #pragma unroll 8
        for (int ch = 0; ch < 128; ch++)
            a += wfin[q * 130 + ch] * wv[ch * 33 + c];
        int base = (((b * 2 + i) * Sz + qbase + q) * 4) * HDz;
        float v = g_vpart[base + c]           * misc[q * 4 + 0]
                + g_vpart[base + HDz + c]     * misc[q * 4 + 1]
                + g_vpart[base + 2 * HDz + c] * misc[q * 4 + 2]
                + g_vpart[base + 3 * HDz + c] * misc[q * 4 + 3];
        g_ctx[(b * Sz + qbase + q) * Hz + hr * HDz + c] = a + v;
    }
}

// ---------------------------------------------------------------------------
// K4: out = ctx @ Wo + bo. Wo staged in smem; 16 rows/CTA, 256 threads.
// ---------------------------------------------------------------------------
__global__ void __launch_bounds__(256) out_kernel(const float* __restrict__ Wo,
                                                  const float* __restrict__ bo,
                                                  float* __restrict__ out) {
    int r0 = blockIdx.x * 16;
    int t = threadIdx.x;
    extern __shared__ float sm4[];
    float* ws = sm4;                 // 128*128
    float* xs = sm4 + Hz * Hz;       // 16*128

    #pragma unroll
    for (int jj = 0; jj < 16; jj++) {
        int idx = jj * 256 + t;
        *(float4*)&ws[idx * 4] = *(const float4*)&Wo[idx * 4];
    }
    #pragma unroll
    for (int jj = 0; jj < 2; jj++) {
        int idx = jj * 256 + t;
        *(float4*)&xs[idx * 4] = *(const float4*)&g_ctx[r0 * Hz + idx * 4];
    }
    __syncthreads();

    int j = t & 127, rbase = (t >> 7) * 8;
    float a[8];
    float bj = bo[j];
    #pragma unroll
    for (int r = 0; r < 8; r++) a[r] = bj;
    #pragma unroll 4
    for (int i = 0; i < Hz; i++) {
        float w = ws[i * Hz + j];
        #pragma unroll
        for (int r = 0; r < 8; r++)
            a[r] += xs[(rbase + r) * Hz + i] * w;
    }
    #pragma unroll
    for (int r = 0; r < 8; r++)
        out[(r0 + rbase + r) * Hz + j] = a[r];
}

// ---------------------------------------------------------------------------
extern "C" void kernel_launch(void* const* d_in, const int* in_sizes, int n_in,
                              void* d_out, int out_size) {
    const float* X    = (const float*)d_in[0];
    const float* mask = (const float*)d_in[1];
    const float* abs0 = (const float*)d_in[2];
    const float* abs1 = (const float*)d_in[3];
    const float* rel0 = (const float*)d_in[4];
    const float* rel1 = (const float*)d_in[5];
    const float* Wq   = (const float*)d_in[6];
    const float* bq   = (const float*)d_in[7];
    const float* Wk   = (const float*)d_in[8];
    const float* bk   = (const float*)d_in[9];
    const float* Wv   = (const float*)d_in[10];
    const float* bv   = (const float*)d_in[11];
    const float* Wo   = (const float*)d_in[12];
    const float* bo   = (const float*)d_in[13];
    float* out = (float*)d_out;

    size_t prsm  = (size_t)(3 * 16 * XPAD + 3 * 32 * Hz) * sizeof(float);
    size_t sbsm  = (size_t)(32 * 32 + 256 * 33 + 32 * SST) * sizeof(float);
    size_t relsm = (size_t)(64 * TST + 128 + 64 + 64 + 4 + 4 + 128) * sizeof(float);
    size_t cbsm  = (size_t)(128 * 33 + 8 * 130 + 96) * sizeof(float);
    size_t outsm = (size_t)(Hz * Hz + 16 * Hz) * sizeof(float);
    cudaFuncSetAttribute(proj_kernel,    cudaFuncAttributeMaxDynamicSharedMemorySize, (int)prsm);
    cudaFuncSetAttribute(sbase_kernel,   cudaFuncAttributeMaxDynamicSharedMemorySize, (int)sbsm);
    cudaFuncSetAttribute(rel_kernel,     cudaFuncAttributeMaxDynamicSharedMemorySize, (int)relsm);
    cudaFuncSetAttribute(combine_kernel, cudaFuncAttributeMaxDynamicSharedMemorySize, (int)cbsm);
    cudaFuncSetAttribute(out_kernel,     cudaFuncAttributeMaxDynamicSharedMemorySize, (int)outsm);

    proj_kernel<<<BSz / 16, 256, prsm>>>(X, abs0, abs1, Wq, bq, Wk, bk, Wv, bv);
    dim3 gs(8, Bz, 4);
    sbase_kernel<<<gs, 256, sbsm>>>(mask, Wk);
    dim3 gr(Sz, Bz, 8);                        // z = i*4 + quarter
    rel_kernel<<<gr, 128, relsm>>>(rel0, rel1);
    dim3 gc(32, Bz, 2);                        // 8 q per CTA
    combine_kernel<<<gc, 256, cbsm>>>(Wv, bv);
    out_kernel<<<BSz / 16, 256, outsm>>>(Wo, bo, out);
}